// round 6
// baseline (speedup 1.0000x reference)
#include <cuda_runtime.h>

// LSTM B=8192, T=512, I=12, H=20 (i,f,g,o), zero init; Linear(H->10) on h_T.
//
// R6: x-projection precomputed per 4-step chunk into SMEM (bias folded in);
// recurrent inner loop does only the h-part with h-weights in registers
// (40 u64/thread). 3 blocks/SM via __launch_bounds__(160,3).
//
//  - Block: 160 threads (5 warps), BPB=16, grid=512.
//  - Inner thread = unit u (4 gate rows) x 2 batch-pairs (bA=g, bB=g+8).
//  - Inner step: 80 fma2, 10 LDS.128 (h) + 2 LDS.128 (xproj), epilogue.
//  - Chunk phase thread = gate row r x 8 batches: 192 fma2, broadcast x loads.

#define LSTM_H   20
#define LSTM_I   12
#define LSTM_T   512
#define BPB      16
#define THREADS  160
#define GRID     512
#define XROW     52      // xs row stride (floats) per batch: 4 steps x 12 + pad
#define PSLOT    84      // xproj (b,t)-slot stride in floats (21 float4 = 336B)

typedef unsigned long long u64;

__device__ __forceinline__ void unpack2(u64 v, float& lo, float& hi) {
    asm("mov.b64 {%0, %1}, %2;" : "=f"(lo), "=f"(hi) : "l"(v));
}
__device__ __forceinline__ u64 fma2(u64 a, u64 b, u64 c) {
    u64 r; asm("fma.rn.f32x2 %0, %1, %2, %3;" : "=l"(r) : "l"(a), "l"(b), "l"(c));
    return r;
}
__device__ __forceinline__ float tanhA(float x) {
    float y; asm("tanh.approx.f32 %0, %1;" : "=f"(y) : "f"(x)); return y;
}
__device__ __forceinline__ float sigA(float x) {
    return fmaf(tanhA(0.5f * x), 0.5f, 0.5f);
}

__global__ void __launch_bounds__(THREADS, 3)
lstm_kernel(const float* __restrict__ x,
            const float* __restrict__ w_ih,
            const float* __restrict__ w_hh,
            const float* __restrict__ b_ih,
            const float* __restrict__ b_hh,
            const float* __restrict__ w_out,
            const float* __restrict__ b_out,
            float* __restrict__ out)
{
    __shared__ __align__(16) float wih_s[80 * LSTM_I];        //  3840 B
    __shared__ __align__(16) float whh_s[80 * LSTM_H];        //  6400 B
    __shared__ __align__(16) float hbuf[2][BPB * LSTM_H];     //  2560 B
    __shared__ __align__(16) float xs[BPB * XROW];            //  3328 B
    __shared__ __align__(16) float xproj[BPB * 4 * PSLOT];    // 21504 B

    const int tid  = threadIdx.x;
    const int lane = tid & 31;
    const int wg   = tid >> 5;          // 0..4
    const int usub = lane >> 3;         // 0..3
    const int g    = lane & 7;          // batch group
    const int u    = 4 * wg + usub;     // unit 0..19
    const int bA   = g, bB = g + 8;
    const int b0   = blockIdx.x * BPB;

    // producer identity for xproj phase: gate row pr, batch-half phf
    const int pr  = (tid < 80) ? tid : tid - 80;
    const int phf = (tid < 80) ? 0 : 1;
    const int uu  = pr % LSTM_H;        // unit of row
    const int qq  = pr / LSTM_H;        // gate class 0..3 (i,f,g,o)
    const float pbias = b_ih[pr] + b_hh[pr];

    // ---- stage weights to SMEM ----
    for (int i = tid; i < 80 * LSTM_I; i += THREADS) wih_s[i] = w_ih[i];
    for (int i = tid; i < 80 * LSTM_H; i += THREADS) whh_s[i] = w_hh[i];
    for (int i = tid; i < BPB * LSTM_H; i += THREADS) hbuf[0][i] = 0.f;
    __syncthreads();

    // ---- h-part weights into registers (40 u64) ----
    u64 whI[10], whF[10], whG[10], whO[10];
    {
        const u64* wh0 = (const u64*)&whh_s[(0 * LSTM_H + u) * LSTM_H];
        const u64* wh1 = (const u64*)&whh_s[(1 * LSTM_H + u) * LSTM_H];
        const u64* wh2 = (const u64*)&whh_s[(2 * LSTM_H + u) * LSTM_H];
        const u64* wh3 = (const u64*)&whh_s[(3 * LSTM_H + u) * LSTM_H];
        #pragma unroll
        for (int k = 0; k < 10; k++) {
            whI[k] = wh0[k]; whF[k] = wh1[k]; whG[k] = wh2[k]; whO[k] = wh3[k];
        }
    }

    // ---- x prefetch: 192 float4 items per 4-step chunk, 160 threads ----
    const float4* x4 = (const float4*)x;
    const int i0 = tid, i1 = tid + THREADS;
    const int pb0 = i0 / 12, pq0 = i0 - pb0 * 12;
    const int pb1 = i1 / 12, pq1 = i1 - pb1 * 12;
    const bool has1 = (i1 < BPB * 12);
    const long gbase0 = (long)(b0 + pb0) * 1536 + pq0;
    const long gbase1 = (long)(b0 + pb1) * 1536 + pq1;
    float4 pf0, pf1;

    // chunk 0 -> xs directly; prefetch chunk 1 into regs
    {
        float4 v = x4[gbase0];
        *(float4*)&xs[pb0 * XROW + 4 * pq0] = v;
        if (has1) {
            float4 v1 = x4[gbase1];
            *(float4*)&xs[pb1 * XROW + 4 * pq1] = v1;
        }
        pf0 = x4[gbase0 + 12];
        if (has1) pf1 = x4[gbase1 + 12];
    }
    __syncthreads();

    // ---- xproj for chunk 0 ----
    {
        const u64* wr = (const u64*)&wih_s[pr * LSTM_I];
        u64 w0 = wr[0], w1 = wr[1], w2 = wr[2], w3 = wr[3], w4 = wr[4], w5 = wr[5];
        #pragma unroll
        for (int b8 = 0; b8 < 8; b8++) {
            const int b = phf * 8 + b8;
            const u64* xr = (const u64*)&xs[b * XROW];
            #pragma unroll
            for (int t4 = 0; t4 < 4; t4++) {
                const u64* xrt = xr + t4 * 6;
                u64 a0 = 0, a1 = 0;
                a0 = fma2(w0, xrt[0], a0); a1 = fma2(w1, xrt[1], a1);
                a0 = fma2(w2, xrt[2], a0); a1 = fma2(w3, xrt[3], a1);
                a0 = fma2(w4, xrt[4], a0); a1 = fma2(w5, xrt[5], a1);
                float l0, h0, l1, h1;
                unpack2(a0, l0, h0); unpack2(a1, l1, h1);
                xproj[(b * 4 + t4) * PSLOT + uu * 4 + qq] = l0 + h0 + l1 + h1 + pbias;
            }
        }
    }
    __syncthreads();

    float cA = 0.f, cB = 0.f;

    #pragma unroll 1
    for (int t = 0; t < LSTM_T; t++) {
        const int tt = t & 3;
        if (tt == 0 && t > 0) {
            // stage prefetched chunk to xs; launch next chunk's GMEM loads
            *(float4*)&xs[pb0 * XROW + 4 * pq0] = pf0;
            if (has1) *(float4*)&xs[pb1 * XROW + 4 * pq1] = pf1;
            if (t + 4 < LSTM_T) {
                pf0 = x4[gbase0 + (long)(t + 4) * 3];
                if (has1) pf1 = x4[gbase1 + (long)(t + 4) * 3];
            }
            __syncthreads();
            // compute xproj for this chunk
            {
                const u64* wr = (const u64*)&wih_s[pr * LSTM_I];
                u64 w0 = wr[0], w1 = wr[1], w2 = wr[2], w3 = wr[3], w4 = wr[4], w5 = wr[5];
                #pragma unroll
                for (int b8 = 0; b8 < 8; b8++) {
                    const int b = phf * 8 + b8;
                    const u64* xr = (const u64*)&xs[b * XROW];
                    #pragma unroll
                    for (int t4 = 0; t4 < 4; t4++) {
                        const u64* xrt = xr + t4 * 6;
                        u64 a0 = 0, a1 = 0;
                        a0 = fma2(w0, xrt[0], a0); a1 = fma2(w1, xrt[1], a1);
                        a0 = fma2(w2, xrt[2], a0); a1 = fma2(w3, xrt[3], a1);
                        a0 = fma2(w4, xrt[4], a0); a1 = fma2(w5, xrt[5], a1);
                        float l0, h0, l1, h1;
                        unpack2(a0, l0, h0); unpack2(a1, l1, h1);
                        xproj[(b * 4 + t4) * PSLOT + uu * 4 + qq] = l0 + h0 + l1 + h1 + pbias;
                    }
                }
            }
            __syncthreads();
        }

        const int cur = t & 1, nxt = cur ^ 1;

        // xproj for this thread's (pair, unit): float4 = gates (i,f,g,o)
        const float4 xpA = *(const float4*)&xproj[(bA * 4 + tt) * PSLOT + u * 4];
        const float4 xpB = *(const float4*)&xproj[(bB * 4 + tt) * PSLOT + u * 4];

        u64 aA0 = 0, aA1 = 0, aA2 = 0, aA3 = 0;
        u64 aB0 = 0, aB1 = 0, aB2 = 0, aB3 = 0;

        // ---- h part: 10 u64 per pair ----
        {
            const u64* hrA = (const u64*)&hbuf[cur][bA * LSTM_H];
            const u64* hrB = (const u64*)&hbuf[cur][bB * LSTM_H];
            #pragma unroll
            for (int k = 0; k < 10; k += 2) {
                ulonglong2 hA = *(const ulonglong2*)(hrA + k);
                ulonglong2 hB = *(const ulonglong2*)(hrB + k);
                aA0 = fma2(whI[k], hA.x, aA0); aA0 = fma2(whI[k+1], hA.y, aA0);
                aA1 = fma2(whF[k], hA.x, aA1); aA1 = fma2(whF[k+1], hA.y, aA1);
                aA2 = fma2(whG[k], hA.x, aA2); aA2 = fma2(whG[k+1], hA.y, aA2);
                aA3 = fma2(whO[k], hA.x, aA3); aA3 = fma2(whO[k+1], hA.y, aA3);
                aB0 = fma2(whI[k], hB.x, aB0); aB0 = fma2(whI[k+1], hB.y, aB0);
                aB1 = fma2(whF[k], hB.x, aB1); aB1 = fma2(whF[k+1], hB.y, aB1);
                aB2 = fma2(whG[k], hB.x, aB2); aB2 = fma2(whG[k+1], hB.y, aB2);
                aB3 = fma2(whO[k], hB.x, aB3); aB3 = fma2(whO[k+1], hB.y, aB3);
            }
        }

        // ---- horizontal add + xproj (bias folded) + cell update ----
        {
            float lo, hi;
            unpack2(aA0, lo, hi); float gi = lo + hi + xpA.x;
            unpack2(aA1, lo, hi); float gf = lo + hi + xpA.y;
            unpack2(aA2, lo, hi); float gg = lo + hi + xpA.z;
            unpack2(aA3, lo, hi); float go = lo + hi + xpA.w;
            cA = sigA(gf) * cA + sigA(gi) * tanhA(gg);
            hbuf[nxt][bA * LSTM_H + u] = sigA(go) * tanhA(cA);
        }
        {
            float lo, hi;
            unpack2(aB0, lo, hi); float gi = lo + hi + xpB.x;
            unpack2(aB1, lo, hi); float gf = lo + hi + xpB.y;
            unpack2(aB2, lo, hi); float gg = lo + hi + xpB.z;
            unpack2(aB3, lo, hi); float go = lo + hi + xpB.w;
            cB = sigA(gf) * cB + sigA(gi) * tanhA(gg);
            hbuf[nxt][bB * LSTM_H + u] = sigA(go) * tanhA(cB);
        }
        __syncthreads();
    }

    // ---- output Linear (final h in hbuf[0]: t=511 -> nxt=0) ----
    {
        const int bl = tid / 10, k = tid - bl * 10;   // 16 x 10 = 160
        float sum = b_out[k];
        #pragma unroll
        for (int j = 0; j < LSTM_H; j++)
            sum = fmaf(hbuf[0][bl * LSTM_H + j], w_out[k * LSTM_H + j], sum);
        out[(long)(b0 + bl) * 10 + k] = sum;
    }
}

extern "C" void kernel_launch(void* const* d_in, const int* in_sizes, int n_in,
                              void* d_out, int out_size)
{
    const float* x     = (const float*)d_in[0];
    const float* w_ih  = (const float*)d_in[1];
    const float* w_hh  = (const float*)d_in[2];
    const float* b_ih  = (const float*)d_in[3];
    const float* b_hh  = (const float*)d_in[4];
    const float* w_out = (const float*)d_in[5];
    const float* b_out = (const float*)d_in[6];
    float* out = (float*)d_out;

    lstm_kernel<<<GRID, THREADS>>>(x, w_ih, w_hh, b_ih, b_hh, w_out, b_out, out);
}

// round 7
// speedup vs baseline: 1.0931x; 1.0931x over previous
#include <cuda_runtime.h>

// LSTM B=8192, T=512, I=12, H=20 (i,f,g,o), zero init; Linear(H->10) on h_T.
//
// R7: h-part weights in registers (40 u64), x-part inline each step with
// x-weights from SMEM (12 LDS.128, broadcast). No producer phases, one
// barrier per step. 3 blocks/SM via __launch_bounds__(160,3).
//
//  - Block: 160 threads (5 warps), BPB=16, grid=512.
//  - Thread = unit u (4 gate rows) x 2 batch-pairs (bA=g, bB=g+8), f32x2 over k.
//  - Thread/step: 128 fma2, 28 LDS.128 (10 h + 6 x-act + 12 x-weight), epilogue.

#define LSTM_H   20
#define LSTM_I   12
#define LSTM_T   512
#define BPB      16
#define THREADS  160
#define GRID     512
#define XROW     52      // xs row stride (floats): 4 steps x 12 + pad (208B, 13x16B)

typedef unsigned long long u64;

__device__ __forceinline__ void unpack2(u64 v, float& lo, float& hi) {
    asm("mov.b64 {%0, %1}, %2;" : "=f"(lo), "=f"(hi) : "l"(v));
}
__device__ __forceinline__ u64 fma2(u64 a, u64 b, u64 c) {
    u64 r; asm("fma.rn.f32x2 %0, %1, %2, %3;" : "=l"(r) : "l"(a), "l"(b), "l"(c));
    return r;
}
__device__ __forceinline__ float tanhA(float x) {
    float y; asm("tanh.approx.f32 %0, %1;" : "=f"(y) : "f"(x)); return y;
}
__device__ __forceinline__ float sigA(float x) {
    return fmaf(tanhA(0.5f * x), 0.5f, 0.5f);
}

__global__ void __launch_bounds__(THREADS, 3)
lstm_kernel(const float* __restrict__ x,
            const float* __restrict__ w_ih,
            const float* __restrict__ w_hh,
            const float* __restrict__ b_ih,
            const float* __restrict__ b_hh,
            const float* __restrict__ w_out,
            const float* __restrict__ b_out,
            float* __restrict__ out)
{
    __shared__ __align__(16) float wih_s[80 * LSTM_I];        // 3840 B
    __shared__ __align__(16) float whh_s[80 * LSTM_H];        // 6400 B
    __shared__ __align__(16) float hbuf[2][BPB * LSTM_H];     // 2560 B
    __shared__ __align__(16) float xs[BPB * XROW];            // 3328 B

    const int tid  = threadIdx.x;
    const int lane = tid & 31;
    const int wg   = tid >> 5;          // 0..4
    const int usub = lane >> 3;         // 0..3
    const int g    = lane & 7;          // batch group
    const int u    = 4 * wg + usub;     // unit 0..19
    const int bA   = g, bB = g + 8;
    const int b0   = blockIdx.x * BPB;

    // ---- stage weights to SMEM ----
    for (int i = tid; i < 80 * LSTM_I; i += THREADS) wih_s[i] = w_ih[i];
    for (int i = tid; i < 80 * LSTM_H; i += THREADS) whh_s[i] = w_hh[i];
    for (int i = tid; i < BPB * LSTM_H; i += THREADS) hbuf[0][i] = 0.f;

    // scalar biases (epilogue adds)
    const float bI = b_ih[0 * LSTM_H + u] + b_hh[0 * LSTM_H + u];
    const float bF = b_ih[1 * LSTM_H + u] + b_hh[1 * LSTM_H + u];
    const float bG = b_ih[2 * LSTM_H + u] + b_hh[2 * LSTM_H + u];
    const float bO = b_ih[3 * LSTM_H + u] + b_hh[3 * LSTM_H + u];

    __syncthreads();

    // ---- h-part weights into registers (40 u64 = 80 regs) ----
    u64 whI[10], whF[10], whG[10], whO[10];
    {
        const u64* wh0 = (const u64*)&whh_s[(0 * LSTM_H + u) * LSTM_H];
        const u64* wh1 = (const u64*)&whh_s[(1 * LSTM_H + u) * LSTM_H];
        const u64* wh2 = (const u64*)&whh_s[(2 * LSTM_H + u) * LSTM_H];
        const u64* wh3 = (const u64*)&whh_s[(3 * LSTM_H + u) * LSTM_H];
        #pragma unroll
        for (int k = 0; k < 10; k++) {
            whI[k] = wh0[k]; whF[k] = wh1[k]; whG[k] = wh2[k]; whO[k] = wh3[k];
        }
    }

    // x-weight row pointers (SMEM, loaded per step)
    const u64* xw0 = (const u64*)&wih_s[(0 * LSTM_H + u) * LSTM_I];
    const u64* xw1 = (const u64*)&wih_s[(1 * LSTM_H + u) * LSTM_I];
    const u64* xw2 = (const u64*)&wih_s[(2 * LSTM_H + u) * LSTM_I];
    const u64* xw3 = (const u64*)&wih_s[(3 * LSTM_H + u) * LSTM_I];

    // ---- x prefetch: 192 float4 items per 4-step chunk, 160 threads ----
    const float4* x4 = (const float4*)x;
    const int i0 = tid, i1 = tid + THREADS;
    const int pb0 = i0 / 12, pq0 = i0 - pb0 * 12;
    const int pb1 = i1 / 12, pq1 = i1 - pb1 * 12;
    const bool has1 = (i1 < BPB * 12);
    const long gbase0 = (long)(b0 + pb0) * 1536 + pq0;
    const long gbase1 = (long)(b0 + pb1) * 1536 + pq1;
    float4 pf0, pf1;

    // chunk 0 -> xs directly; prefetch chunk 1 into regs
    {
        float4 v = x4[gbase0];
        *(float4*)&xs[pb0 * XROW + 4 * pq0] = v;
        if (has1) {
            float4 v1 = x4[gbase1];
            *(float4*)&xs[pb1 * XROW + 4 * pq1] = v1;
        }
        pf0 = x4[gbase0 + 12];
        if (has1) pf1 = x4[gbase1 + 12];
    }
    __syncthreads();

    float cA = 0.f, cB = 0.f;

    #pragma unroll 1
    for (int t = 0; t < LSTM_T; t++) {
        const int tt = t & 3;
        if (tt == 0 && t > 0) {
            // previous step's barrier guarantees chunk consumed; stage & refill
            *(float4*)&xs[pb0 * XROW + 4 * pq0] = pf0;
            if (has1) *(float4*)&xs[pb1 * XROW + 4 * pq1] = pf1;
            if (t + 4 < LSTM_T) {
                pf0 = x4[gbase0 + (long)(t + 4) * 3];
                if (has1) pf1 = x4[gbase1 + (long)(t + 4) * 3];
            }
            __syncthreads();
        }

        const int cur = t & 1, nxt = cur ^ 1;

        u64 aA0 = 0, aA1 = 0, aA2 = 0, aA3 = 0;
        u64 aB0 = 0, aB1 = 0, aB2 = 0, aB3 = 0;

        // ---- x part: 6 u64 per batch, weights from SMEM ----
        {
            const u64* xrA = (const u64*)&xs[bA * XROW + tt * LSTM_I];
            const u64* xrB = (const u64*)&xs[bB * XROW + tt * LSTM_I];
            #pragma unroll
            for (int k = 0; k < 6; k += 2) {
                ulonglong2 w0 = *(const ulonglong2*)(xw0 + k);
                ulonglong2 w1 = *(const ulonglong2*)(xw1 + k);
                ulonglong2 w2 = *(const ulonglong2*)(xw2 + k);
                ulonglong2 w3 = *(const ulonglong2*)(xw3 + k);
                ulonglong2 xA = *(const ulonglong2*)(xrA + k);
                ulonglong2 xB = *(const ulonglong2*)(xrB + k);
                aA0 = fma2(w0.x, xA.x, aA0); aA0 = fma2(w0.y, xA.y, aA0);
                aA1 = fma2(w1.x, xA.x, aA1); aA1 = fma2(w1.y, xA.y, aA1);
                aA2 = fma2(w2.x, xA.x, aA2); aA2 = fma2(w2.y, xA.y, aA2);
                aA3 = fma2(w3.x, xA.x, aA3); aA3 = fma2(w3.y, xA.y, aA3);
                aB0 = fma2(w0.x, xB.x, aB0); aB0 = fma2(w0.y, xB.y, aB0);
                aB1 = fma2(w1.x, xB.x, aB1); aB1 = fma2(w1.y, xB.y, aB1);
                aB2 = fma2(w2.x, xB.x, aB2); aB2 = fma2(w2.y, xB.y, aB2);
                aB3 = fma2(w3.x, xB.x, aB3); aB3 = fma2(w3.y, xB.y, aB3);
            }
        }

        // ---- h part: 10 u64 per batch, weights in registers ----
        {
            const u64* hrA = (const u64*)&hbuf[cur][bA * LSTM_H];
            const u64* hrB = (const u64*)&hbuf[cur][bB * LSTM_H];
            #pragma unroll
            for (int k = 0; k < 10; k += 2) {
                ulonglong2 hA = *(const ulonglong2*)(hrA + k);
                ulonglong2 hB = *(const ulonglong2*)(hrB + k);
                aA0 = fma2(whI[k], hA.x, aA0); aA0 = fma2(whI[k+1], hA.y, aA0);
                aA1 = fma2(whF[k], hA.x, aA1); aA1 = fma2(whF[k+1], hA.y, aA1);
                aA2 = fma2(whG[k], hA.x, aA2); aA2 = fma2(whG[k+1], hA.y, aA2);
                aA3 = fma2(whO[k], hA.x, aA3); aA3 = fma2(whO[k+1], hA.y, aA3);
                aB0 = fma2(whI[k], hB.x, aB0); aB0 = fma2(whI[k+1], hB.y, aB0);
                aB1 = fma2(whF[k], hB.x, aB1); aB1 = fma2(whF[k+1], hB.y, aB1);
                aB2 = fma2(whG[k], hB.x, aB2); aB2 = fma2(whG[k+1], hB.y, aB2);
                aB3 = fma2(whO[k], hB.x, aB3); aB3 = fma2(whO[k+1], hB.y, aB3);
            }
        }

        // ---- horizontal add + bias + cell update ----
        {
            float lo, hi;
            unpack2(aA0, lo, hi); float gi = lo + hi + bI;
            unpack2(aA1, lo, hi); float gf = lo + hi + bF;
            unpack2(aA2, lo, hi); float gg = lo + hi + bG;
            unpack2(aA3, lo, hi); float go = lo + hi + bO;
            cA = sigA(gf) * cA + sigA(gi) * tanhA(gg);
            hbuf[nxt][bA * LSTM_H + u] = sigA(go) * tanhA(cA);
        }
        {
            float lo, hi;
            unpack2(aB0, lo, hi); float gi = lo + hi + bI;
            unpack2(aB1, lo, hi); float gf = lo + hi + bF;
            unpack2(aB2, lo, hi); float gg = lo + hi + bG;
            unpack2(aB3, lo, hi); float go = lo + hi + bO;
            cB = sigA(gf) * cB + sigA(gi) * tanhA(gg);
            hbuf[nxt][bB * LSTM_H + u] = sigA(go) * tanhA(cB);
        }
        __syncthreads();
    }

    // ---- output Linear (final h in hbuf[0]: t=511 -> nxt=0) ----
    {
        const int bl = tid / 10, k = tid - bl * 10;   // 16 x 10 = 160
        float sum = b_out[k];
        #pragma unroll
        for (int j = 0; j < LSTM_H; j++)
            sum = fmaf(hbuf[0][bl * LSTM_H + j], w_out[k * LSTM_H + j], sum);
        out[(long)(b0 + bl) * 10 + k] = sum;
    }
}

extern "C" void kernel_launch(void* const* d_in, const int* in_sizes, int n_in,
                              void* d_out, int out_size)
{
    const float* x     = (const float*)d_in[0];
    const float* w_ih  = (const float*)d_in[1];
    const float* w_hh  = (const float*)d_in[2];
    const float* b_ih  = (const float*)d_in[3];
    const float* b_hh  = (const float*)d_in[4];
    const float* w_out = (const float*)d_in[5];
    const float* b_out = (const float*)d_in[6];
    float* out = (float*)d_out;

    lstm_kernel<<<GRID, THREADS>>>(x, w_ih, w_hh, b_ih, b_hh, w_out, b_out, out);
}

// round 9
// speedup vs baseline: 1.2289x; 1.1243x over previous
#include <cuda_runtime.h>

// LSTM B=8192, T=512, I=12, H=20 (i,f,g,o), zero init; Linear(H->10) on h_T.
//
// R9 (= R8, compile fixed): Q=4 batches/thread x 1 unit (4 gate rows), full k,
// ALL weights in registers (64 u64/thread). Inner loop reads only activations.
//  - Block: 160 threads = 8 quads x 20 units, BPB=32, grid=256 (one wave,
//    2 blocks/SM). __launch_bounds__(160,2) caps regs at 204.
//  - x staged per 4-step chunk via cp.async double-buffer.
//  - Per-batch epilogue immediately after its fma block -> acc regs reused.

#define LSTM_H   20
#define LSTM_I   12
#define LSTM_T   512
#define BPB      32
#define THREADS  160
#define GRID     256
#define XROW     52    // floats per batch row in xs: 48 data + 4 pad

typedef unsigned long long u64;
typedef unsigned int       u32;

__device__ __forceinline__ void unpack2(u64 v, float& lo, float& hi) {
    asm("mov.b64 {%0, %1}, %2;" : "=f"(lo), "=f"(hi) : "l"(v));
}
__device__ __forceinline__ u64 fma2(u64 a, u64 b, u64 c) {
    u64 r; asm("fma.rn.f32x2 %0, %1, %2, %3;" : "=l"(r) : "l"(a), "l"(b), "l"(c));
    return r;
}
__device__ __forceinline__ float tanhA(float x) {
    float y; asm("tanh.approx.f32 %0, %1;" : "=f"(y) : "f"(x)); return y;
}
__device__ __forceinline__ float sigA(float x) {
    return fmaf(tanhA(0.5f * x), 0.5f, 0.5f);
}
__device__ __forceinline__ void cp_async16(u32 smem_dst, const void* gsrc) {
    asm volatile("cp.async.ca.shared.global [%0], [%1], 16;\n"
                 :: "r"(smem_dst), "l"(gsrc) : "memory");
}
__device__ __forceinline__ void cp_commit() {
    asm volatile("cp.async.commit_group;\n" ::: "memory");
}
template<int N>
__device__ __forceinline__ void cp_wait() {
    asm volatile("cp.async.wait_group %0;\n" :: "n"(N) : "memory");
}

__global__ void __launch_bounds__(THREADS, 2)
lstm_kernel(const float* __restrict__ x,
            const float* __restrict__ w_ih,
            const float* __restrict__ w_hh,
            const float* __restrict__ b_ih,
            const float* __restrict__ b_hh,
            const float* __restrict__ w_out,
            const float* __restrict__ b_out,
            float* __restrict__ out)
{
    __shared__ __align__(16) float wcomb[80 * 32];           // 10240 B: [row][x 0..11 | h 12..31]
    __shared__ __align__(16) float hbuf[2][BPB * LSTM_H];    //  5120 B
    __shared__ __align__(16) float xs[2][BPB * XROW];        // 13312 B

    const int tid  = threadIdx.x;
    const int u    = tid % 20;          // unit
    const int quad = tid / 20;          // 0..7 -> batches 4*quad..4*quad+3
    const int b0   = blockIdx.x * BPB;

    // ---- stage combined weight rows into SMEM ----
    for (int i = tid; i < 80 * LSTM_I; i += THREADS) {
        int r = i / LSTM_I, k = i - r * LSTM_I;
        wcomb[r * 32 + k] = w_ih[i];
    }
    for (int i = tid; i < 80 * LSTM_H; i += THREADS) {
        int r = i / LSTM_H, k = i - r * LSTM_H;
        wcomb[r * 32 + 12 + k] = w_hh[i];
    }
    for (int i = tid; i < BPB * LSTM_H; i += THREADS) hbuf[0][i] = 0.f;

    const float bI = b_ih[0 * 20 + u] + b_hh[0 * 20 + u];
    const float bF = b_ih[1 * 20 + u] + b_hh[1 * 20 + u];
    const float bG = b_ih[2 * 20 + u] + b_hh[2 * 20 + u];
    const float bO = b_ih[3 * 20 + u] + b_hh[3 * 20 + u];

    // ---- cp.async: chunk 0 -> xs[0], chunk 1 -> xs[1] ----
    const float4* x4 = (const float4*)x;
    const u32 xs_base = (u32)__cvta_generic_to_shared(&xs[0][0]);
    {
        #pragma unroll 1
        for (int e = tid; e < BPB * 12; e += THREADS) {
            int b = e / 12, q = e - b * 12;
            cp_async16(xs_base + (u32)((b * XROW + q * 4) * 4),
                       x4 + (long)(b0 + b) * 1536 + q);
        }
        cp_commit();
        #pragma unroll 1
        for (int e = tid; e < BPB * 12; e += THREADS) {
            int b = e / 12, q = e - b * 12;
            cp_async16(xs_base + (u32)((BPB * XROW + b * XROW + q * 4) * 4),
                       x4 + (long)(b0 + b) * 1536 + 12 + q);
        }
        cp_commit();
    }
    cp_wait<1>();          // chunk 0 landed
    __syncthreads();       // wcomb + hbuf + chunk0 visible to all

    // ---- copy this unit's 4 gate rows to registers (64 u64 = 128 regs) ----
    u64 wI[16], wF[16], wG[16], wO[16];
    {
        const u64* r0 = (const u64*)&wcomb[(0 * 20 + u) * 32];
        const u64* r1 = (const u64*)&wcomb[(1 * 20 + u) * 32];
        const u64* r2 = (const u64*)&wcomb[(2 * 20 + u) * 32];
        const u64* r3 = (const u64*)&wcomb[(3 * 20 + u) * 32];
        #pragma unroll
        for (int k = 0; k < 16; k++) {
            wI[k] = r0[k]; wF[k] = r1[k]; wG[k] = r2[k]; wO[k] = r3[k];
        }
    }

    float cst[4] = {0.f, 0.f, 0.f, 0.f};

    #pragma unroll 1
    for (int t = 0; t < LSTM_T; t++) {
        const int tt = t & 3;
        if (tt == 0 && t > 0) {
            cp_wait<0>();          // current chunk fully landed
            __syncthreads();
            if (t + 4 < LSTM_T) {  // prefetch next chunk into the other buffer
                const int nbuf = ((t >> 2) + 1) & 1;
                #pragma unroll 1
                for (int e = tid; e < BPB * 12; e += THREADS) {
                    int b = e / 12, q = e - b * 12;
                    cp_async16(xs_base + (u32)((nbuf * BPB * XROW + b * XROW + q * 4) * 4),
                               x4 + (long)(b0 + b) * 1536 + (long)(t + 4) * 3 + q);
                }
                cp_commit();
            }
        }

        const int buf = (t >> 2) & 1;
        const int cur = t & 1, nxt = cur ^ 1;

        #pragma unroll
        for (int j = 0; j < 4; j++) {
            const int b = quad * 4 + j;

            // activations: x 6 u64 + h 10 u64 = 8 LDS.128
            u64 av[16];
            {
                const u64* xr = (const u64*)&xs[buf][b * XROW + tt * 12];
                ulonglong2 v0 = *(const ulonglong2*)(xr + 0);
                ulonglong2 v1 = *(const ulonglong2*)(xr + 2);
                ulonglong2 v2 = *(const ulonglong2*)(xr + 4);
                av[0] = v0.x; av[1] = v0.y; av[2] = v1.x;
                av[3] = v1.y; av[4] = v2.x; av[5] = v2.y;
                const u64* hr = (const u64*)&hbuf[cur][b * LSTM_H];
                ulonglong2 h0 = *(const ulonglong2*)(hr + 0);
                ulonglong2 h1 = *(const ulonglong2*)(hr + 2);
                ulonglong2 h2 = *(const ulonglong2*)(hr + 4);
                ulonglong2 h3 = *(const ulonglong2*)(hr + 6);
                ulonglong2 h4 = *(const ulonglong2*)(hr + 8);
                av[6]  = h0.x; av[7]  = h0.y; av[8]  = h1.x; av[9]  = h1.y;
                av[10] = h2.x; av[11] = h2.y; av[12] = h3.x; av[13] = h3.y;
                av[14] = h4.x; av[15] = h4.y;
            }

            u64 aI = 0, aF = 0, aG = 0, aO = 0;
            #pragma unroll
            for (int k = 0; k < 16; k++) {
                aI = fma2(wI[k], av[k], aI);
                aF = fma2(wF[k], av[k], aF);
                aG = fma2(wG[k], av[k], aG);
                aO = fma2(wO[k], av[k], aO);
            }

            float lo, hi;
            unpack2(aI, lo, hi); float gi = lo + hi + bI;
            unpack2(aF, lo, hi); float gf = lo + hi + bF;
            unpack2(aG, lo, hi); float gg = lo + hi + bG;
            unpack2(aO, lo, hi); float go = lo + hi + bO;
            float c = sigA(gf) * cst[j] + sigA(gi) * tanhA(gg);
            cst[j] = c;
            hbuf[nxt][b * LSTM_H + u] = sigA(go) * tanhA(c);
        }
        __syncthreads();
    }

    // ---- output Linear (final h in hbuf[0]: t=511 -> nxt=0) ----
    #pragma unroll
    for (int rep = 0; rep < 2; rep++) {
        const int o = tid + rep * THREADS;      // 0..319
        const int bl = o / 10, k = o - bl * 10;
        float sum = b_out[k];
        #pragma unroll
        for (int j = 0; j < LSTM_H; j++)
            sum = fmaf(hbuf[0][bl * LSTM_H + j], w_out[k * LSTM_H + j], sum);
        out[(long)(b0 + bl) * 10 + k] = sum;
    }
}

extern "C" void kernel_launch(void* const* d_in, const int* in_sizes, int n_in,
                              void* d_out, int out_size)
{
    const float* x     = (const float*)d_in[0];
    const float* w_ih  = (const float*)d_in[1];
    const float* w_hh  = (const float*)d_in[2];
    const float* b_ih  = (const float*)d_in[3];
    const float* b_hh  = (const float*)d_in[4];
    const float* w_out = (const float*)d_in[5];
    const float* b_out = (const float*)d_in[6];
    float* out = (float*)d_out;

    lstm_kernel<<<GRID, THREADS>>>(x, w_ih, w_hh, b_ih, b_hh, w_out, b_out, out);
}

// round 10
// speedup vs baseline: 1.3870x; 1.1287x over previous
#include <cuda_runtime.h>

// LSTM B=8192, T=512, I=12, H=20 (i,f,g,o), zero init; Linear(H->10) on h_T.
//
// R10: gate-split weights-in-registers. Thread = 2 gate rows x 1 unit x 4
// batches (32 u64 weights). Partner thread (lane^1) holds the other 2 gates;
// gates combined via 4 scalar shfl.xor(1). Each thread epilogues its 2 owned
// batches (uniform, no divergence).
//  - Block: 320 threads = 8 quads x 20 units x 2 gate-halves, BPB=32,
//    grid=256, __launch_bounds__(320,2) -> 2 blocks/SM, 20 warps/SM.
//  - Thread/step: 128 fma2, 32 act LDS.128, 4 shfl, 10 MUFU, 2 STS.
//  - x staged per 4-step chunk via cp.async double-buffer.

#define LSTM_H   20
#define LSTM_I   12
#define LSTM_T   512
#define BPB      32
#define THREADS  320
#define GRID     256
#define XROW     52    // floats per batch row in xs (208B, 16B-aligned)

typedef unsigned long long u64;
typedef unsigned int       u32;

__device__ __forceinline__ void unpack2(u64 v, float& lo, float& hi) {
    asm("mov.b64 {%0, %1}, %2;" : "=f"(lo), "=f"(hi) : "l"(v));
}
__device__ __forceinline__ u64 fma2(u64 a, u64 b, u64 c) {
    u64 r; asm("fma.rn.f32x2 %0, %1, %2, %3;" : "=l"(r) : "l"(a), "l"(b), "l"(c));
    return r;
}
__device__ __forceinline__ float hadd2(u64 v) {
    float lo, hi; unpack2(v, lo, hi); return lo + hi;
}
__device__ __forceinline__ float tanhA(float x) {
    float y; asm("tanh.approx.f32 %0, %1;" : "=f"(y) : "f"(x)); return y;
}
__device__ __forceinline__ float sigA(float x) {
    return fmaf(tanhA(0.5f * x), 0.5f, 0.5f);
}
__device__ __forceinline__ void cp_async16(u32 smem_dst, const void* gsrc) {
    asm volatile("cp.async.ca.shared.global [%0], [%1], 16;\n"
                 :: "r"(smem_dst), "l"(gsrc) : "memory");
}
__device__ __forceinline__ void cp_commit() {
    asm volatile("cp.async.commit_group;\n" ::: "memory");
}
template<int N>
__device__ __forceinline__ void cp_wait() {
    asm volatile("cp.async.wait_group %0;\n" :: "n"(N) : "memory");
}

__global__ void __launch_bounds__(THREADS, 2)
lstm_kernel(const float* __restrict__ x,
            const float* __restrict__ w_ih,
            const float* __restrict__ w_hh,
            const float* __restrict__ b_ih,
            const float* __restrict__ b_hh,
            const float* __restrict__ w_out,
            const float* __restrict__ b_out,
            float* __restrict__ out)
{
    __shared__ __align__(16) float wcomb[80 * 32];           // 10240 B: [row][x0..11 | h12..31]
    __shared__ __align__(16) float hbuf[2][BPB * LSTM_H];    //  5120 B
    __shared__ __align__(16) float xs[2][BPB * XROW];        // 13312 B

    const int tid  = threadIdx.x;
    const int quad = tid / 40;          // 0..7 -> batches 4*quad..4*quad+3
    const int r    = tid % 40;
    const int u    = r >> 1;            // unit 0..19
    const int gh   = r & 1;             // gate-half: 0 -> rows (i,g), 1 -> rows (f,o)
    const int b0   = blockIdx.x * BPB;
    const int q4   = quad * 4;

    // this thread's two gate rows
    const int row0 = gh ? (20 + u) : u;          // f : i
    const int row1 = gh ? (60 + u) : (40 + u);   // o : g

    // ---- stage combined weight rows into SMEM ----
    for (int i = tid; i < 80 * LSTM_I; i += THREADS) {
        int rr = i / LSTM_I, k = i - rr * LSTM_I;
        wcomb[rr * 32 + k] = w_ih[i];
    }
    for (int i = tid; i < 80 * LSTM_H; i += THREADS) {
        int rr = i / LSTM_H, k = i - rr * LSTM_H;
        wcomb[rr * 32 + 12 + k] = w_hh[i];
    }
    for (int i = tid; i < BPB * LSTM_H; i += THREADS) hbuf[0][i] = 0.f;

    const float bias0 = b_ih[row0] + b_hh[row0];
    const float bias1 = b_ih[row1] + b_hh[row1];

    // ---- cp.async: chunk 0 -> xs[0], chunk 1 -> xs[1] ----
    const float4* x4 = (const float4*)x;
    const u32 xs_base = (u32)__cvta_generic_to_shared(&xs[0][0]);
    {
        #pragma unroll 1
        for (int e = tid; e < BPB * 12; e += THREADS) {
            int b = e / 12, q = e - b * 12;
            cp_async16(xs_base + (u32)((b * XROW + q * 4) * 4),
                       x4 + (long)(b0 + b) * 1536 + q);
        }
        cp_commit();
        #pragma unroll 1
        for (int e = tid; e < BPB * 12; e += THREADS) {
            int b = e / 12, q = e - b * 12;
            cp_async16(xs_base + (u32)((BPB * XROW + b * XROW + q * 4) * 4),
                       x4 + (long)(b0 + b) * 1536 + 12 + q);
        }
        cp_commit();
    }
    cp_wait<1>();          // chunk 0 landed
    __syncthreads();       // wcomb + hbuf + chunk0 visible

    // ---- this thread's 2 gate rows into registers (32 u64 = 64 regs) ----
    u64 w0[16], w1[16];
    {
        const u64* p0 = (const u64*)&wcomb[row0 * 32];
        const u64* p1 = (const u64*)&wcomb[row1 * 32];
        #pragma unroll
        for (int k = 0; k < 16; k++) { w0[k] = p0[k]; w1[k] = p1[k]; }
    }

    // c state for my 2 owned batches: q4 + 2*gh, q4 + 2*gh + 1
    float c0 = 0.f, c1 = 0.f;

    #pragma unroll 1
    for (int t = 0; t < LSTM_T; t++) {
        const int tt = t & 3;
        if (tt == 0 && t > 0) {
            cp_wait<0>();
            __syncthreads();
            if (t + 4 < LSTM_T) {
                const int nbuf = ((t >> 2) + 1) & 1;
                #pragma unroll 1
                for (int e = tid; e < BPB * 12; e += THREADS) {
                    int b = e / 12, q = e - b * 12;
                    cp_async16(xs_base + (u32)((nbuf * BPB * XROW + b * XROW + q * 4) * 4),
                               x4 + (long)(b0 + b) * 1536 + (long)(t + 4) * 3 + q);
                }
                cp_commit();
            }
        }

        const int buf = (t >> 2) & 1;
        const int cur = t & 1, nxt = cur ^ 1;

        // gate scalars for all 4 quad batches (biased): gA = row0-gate, gB = row1-gate
        float gA[4], gB[4];
        #pragma unroll
        for (int j = 0; j < 4; j++) {
            const int b = q4 + j;
            const u64* xr = (const u64*)&xs[buf][b * XROW + tt * 12];
            const u64* hr = (const u64*)&hbuf[cur][b * LSTM_H];
            u64 a0 = 0, a1 = 0;
            #pragma unroll
            for (int k = 0; k < 6; k += 2) {
                ulonglong2 xv = *(const ulonglong2*)(xr + k);
                a0 = fma2(w0[k], xv.x, a0); a0 = fma2(w0[k+1], xv.y, a0);
                a1 = fma2(w1[k], xv.x, a1); a1 = fma2(w1[k+1], xv.y, a1);
            }
            #pragma unroll
            for (int k = 0; k < 10; k += 2) {
                ulonglong2 hv = *(const ulonglong2*)(hr + k);
                a0 = fma2(w0[6+k], hv.x, a0); a0 = fma2(w0[6+k+1], hv.y, a0);
                a1 = fma2(w1[6+k], hv.x, a1); a1 = fma2(w1[6+k+1], hv.y, a1);
            }
            gA[j] = hadd2(a0) + bias0;
            gB[j] = hadd2(a1) + bias1;
        }

        // ---- two exchange+epilogue sections: pairs (0,2) and (1,3) ----
        #pragma unroll
        for (int p = 0; p < 2; p++) {
            // my owned batch in this pair: j = 2*gh + p; partner's: j = 2*(1-gh) + p
            const int jm = 2 * gh + p;          // owned
            const int jp = 2 * (1 - gh) + p;    // partner-owned (what I send)
            float sa = gA[jp], sb = gB[jp];
            float ra = __shfl_xor_sync(0xffffffffu, sa, 1);
            float rb = __shfl_xor_sync(0xffffffffu, sb, 1);
            float la = gA[jm], lb = gB[jm];
            // gh0: local=(i,g), recv=(f,o); gh1: local=(f,o), recv=(i,g)
            float gi = gh ? ra : la;
            float gg = gh ? rb : lb;
            float gf = gh ? la : ra;
            float go = gh ? lb : rb;
            float c  = p ? c1 : c0;
            c = sigA(gf) * c + sigA(gi) * tanhA(gg);
            if (p) c1 = c; else c0 = c;
            float h = sigA(go) * tanhA(c);
            hbuf[nxt][(q4 + jm) * LSTM_H + u] = h;
        }
        __syncthreads();
    }

    // ---- output Linear (final h in hbuf[0]: t=511 -> nxt=0) ----
    {
        const int bl = tid / 10, k = tid - bl * 10;   // 32 x 10 = 320
        float sum = b_out[k];
        #pragma unroll
        for (int j = 0; j < LSTM_H; j++)
            sum = fmaf(hbuf[0][bl * LSTM_H + j], w_out[k * LSTM_H + j], sum);
        out[(long)(b0 + bl) * 10 + k] = sum;
    }
}

extern "C" void kernel_launch(void* const* d_in, const int* in_sizes, int n_in,
                              void* d_out, int out_size)
{
    const float* x     = (const float*)d_in[0];
    const float* w_ih  = (const float*)d_in[1];
    const float* w_hh  = (const float*)d_in[2];
    const float* b_ih  = (const float*)d_in[3];
    const float* b_hh  = (const float*)d_in[4];
    const float* w_out = (const float*)d_in[5];
    const float* b_out = (const float*)d_in[6];
    float* out = (float*)d_out;

    lstm_kernel<<<GRID, THREADS>>>(x, w_ih, w_hh, b_ih, b_hh, w_out, b_out, out);
}

// round 11
// speedup vs baseline: 1.4462x; 1.0427x over previous
#include <cuda_runtime.h>

// LSTM B=8192, T=512, I=12, H=20 (i,f,g,o), zero init; Linear(H->10) on h_T.
//
// R11 = R10 + group-local synchronization. The 320-thread block is two
// independent 160-thread groups (4 quads = 16 batches each): h production and
// consumption is closed within a group, so per-step sync is a named barrier
// (bar.sync 1+gid, 160), and x staging/chunk sync is group-local too.
//  - Thread = 2 gate rows x 1 unit x 4 batches (32 u64 weights in regs).
//    Partner (lane^1) holds the other 2 gates; combined via shfl.xor(1).
//  - Block: 320 thr, BPB=32, grid=256, __launch_bounds__(320,2).
//  - Bias folded into f32x2 accumulator init.

#define LSTM_H   20
#define LSTM_I   12
#define LSTM_T   512
#define BPB      32
#define THREADS  320
#define GRID     256
#define XROW     52    // floats per batch row in xs (208B, 16B-aligned)

typedef unsigned long long u64;
typedef unsigned int       u32;

__device__ __forceinline__ u64 pack2(float lo, float hi) {
    u64 r; asm("mov.b64 %0, {%1, %2};" : "=l"(r) : "f"(lo), "f"(hi)); return r;
}
__device__ __forceinline__ void unpack2(u64 v, float& lo, float& hi) {
    asm("mov.b64 {%0, %1}, %2;" : "=f"(lo), "=f"(hi) : "l"(v));
}
__device__ __forceinline__ u64 fma2(u64 a, u64 b, u64 c) {
    u64 r; asm("fma.rn.f32x2 %0, %1, %2, %3;" : "=l"(r) : "l"(a), "l"(b), "l"(c));
    return r;
}
__device__ __forceinline__ float hadd2(u64 v) {
    float lo, hi; unpack2(v, lo, hi); return lo + hi;
}
__device__ __forceinline__ float tanhA(float x) {
    float y; asm("tanh.approx.f32 %0, %1;" : "=f"(y) : "f"(x)); return y;
}
__device__ __forceinline__ float sigA(float x) {
    return fmaf(tanhA(0.5f * x), 0.5f, 0.5f);
}
__device__ __forceinline__ void cp_async16(u32 smem_dst, const void* gsrc) {
    asm volatile("cp.async.ca.shared.global [%0], [%1], 16;\n"
                 :: "r"(smem_dst), "l"(gsrc) : "memory");
}
__device__ __forceinline__ void cp_commit() {
    asm volatile("cp.async.commit_group;\n" ::: "memory");
}
template<int N>
__device__ __forceinline__ void cp_wait() {
    asm volatile("cp.async.wait_group %0;\n" :: "n"(N) : "memory");
}
__device__ __forceinline__ void group_bar(int id) {
    asm volatile("bar.sync %0, %1;" :: "r"(id), "r"(160) : "memory");
}

__global__ void __launch_bounds__(THREADS, 2)
lstm_kernel(const float* __restrict__ x,
            const float* __restrict__ w_ih,
            const float* __restrict__ w_hh,
            const float* __restrict__ b_ih,
            const float* __restrict__ b_hh,
            const float* __restrict__ w_out,
            const float* __restrict__ b_out,
            float* __restrict__ out)
{
    __shared__ __align__(16) float wcomb[80 * 32];           // 10240 B
    __shared__ __align__(16) float hbuf[2][BPB * LSTM_H];    //  5120 B
    __shared__ __align__(16) float xs[2][BPB * XROW];        // 13312 B

    const int tid  = threadIdx.x;
    const int gid  = tid / 160;          // group 0/1 (owns 16 batches)
    const int ltid = tid - gid * 160;    // 0..159 within group
    const int quad = tid / 40;           // 0..7 (global)
    const int r    = tid % 40;
    const int u    = r >> 1;             // unit 0..19
    const int gh   = r & 1;              // 0 -> rows (i,g), 1 -> rows (f,o)
    const int b0   = blockIdx.x * BPB;
    const int q4   = quad * 4;
    const int barid = 1 + gid;

    const int row0 = gh ? (20 + u) : u;          // f : i
    const int row1 = gh ? (60 + u) : (40 + u);   // o : g

    // ---- stage combined weight rows into SMEM (whole block) ----
    for (int i = tid; i < 80 * LSTM_I; i += THREADS) {
        int rr = i / LSTM_I, k = i - rr * LSTM_I;
        wcomb[rr * 32 + k] = w_ih[i];
    }
    for (int i = tid; i < 80 * LSTM_H; i += THREADS) {
        int rr = i / LSTM_H, k = i - rr * LSTM_H;
        wcomb[rr * 32 + 12 + k] = w_hh[i];
    }
    for (int i = tid; i < BPB * LSTM_H; i += THREADS) hbuf[0][i] = 0.f;

    // bias folded into acc init as (bias, 0)
    const u64 binit0 = pack2(b_ih[row0] + b_hh[row0], 0.f);
    const u64 binit1 = pack2(b_ih[row1] + b_hh[row1], 0.f);

    // ---- cp.async: group loads its own 16 batches, chunk0 -> xs[0], chunk1 -> xs[1] ----
    const float4* x4 = (const float4*)x;
    const u32 xs_base = (u32)__cvta_generic_to_shared(&xs[0][0]);
    {
        #pragma unroll 1
        for (int e = ltid; e < 16 * 12; e += 160) {
            int b = gid * 16 + e / 12, q = e - (e / 12) * 12;
            cp_async16(xs_base + (u32)((b * XROW + q * 4) * 4),
                       x4 + (long)(b0 + b) * 1536 + q);
        }
        cp_commit();
        #pragma unroll 1
        for (int e = ltid; e < 16 * 12; e += 160) {
            int b = gid * 16 + e / 12, q = e - (e / 12) * 12;
            cp_async16(xs_base + (u32)((BPB * XROW + b * XROW + q * 4) * 4),
                       x4 + (long)(b0 + b) * 1536 + 12 + q);
        }
        cp_commit();
    }
    cp_wait<1>();          // chunk 0 landed
    __syncthreads();       // wcomb + hbuf + chunk0 visible to whole block

    // ---- this thread's 2 gate rows into registers (32 u64 = 64 regs) ----
    u64 w0[16], w1[16];
    {
        const u64* p0 = (const u64*)&wcomb[row0 * 32];
        const u64* p1 = (const u64*)&wcomb[row1 * 32];
        #pragma unroll
        for (int k = 0; k < 16; k++) { w0[k] = p0[k]; w1[k] = p1[k]; }
    }

    float c0 = 0.f, c1 = 0.f;   // c for my 2 owned batches: q4+2*gh, q4+2*gh+1

    #pragma unroll 1
    for (int t = 0; t < LSTM_T; t++) {
        const int tt = t & 3;
        if (tt == 0 && t > 0) {
            cp_wait<0>();          // my group's chunk landed
            group_bar(barid);      // group done reading old buffer
            if (t + 4 < LSTM_T) {
                const int nbuf = ((t >> 2) + 1) & 1;
                #pragma unroll 1
                for (int e = ltid; e < 16 * 12; e += 160) {
                    int b = gid * 16 + e / 12, q = e - (e / 12) * 12;
                    cp_async16(xs_base + (u32)((nbuf * BPB * XROW + b * XROW + q * 4) * 4),
                               x4 + (long)(b0 + b) * 1536 + (long)(t + 4) * 3 + q);
                }
                cp_commit();
            }
        }

        const int buf = (t >> 2) & 1;
        const int cur = t & 1, nxt = cur ^ 1;

        // gate scalars for all 4 quad batches (bias pre-folded)
        float gA[4], gB[4];
        #pragma unroll
        for (int j = 0; j < 4; j++) {
            const int b = q4 + j;
            const u64* xr = (const u64*)&xs[buf][b * XROW + tt * 12];
            const u64* hr = (const u64*)&hbuf[cur][b * LSTM_H];
            u64 a0 = binit0, a1 = binit1;
            #pragma unroll
            for (int k = 0; k < 6; k += 2) {
                ulonglong2 xv = *(const ulonglong2*)(xr + k);
                a0 = fma2(w0[k], xv.x, a0); a0 = fma2(w0[k+1], xv.y, a0);
                a1 = fma2(w1[k], xv.x, a1); a1 = fma2(w1[k+1], xv.y, a1);
            }
            #pragma unroll
            for (int k = 0; k < 10; k += 2) {
                ulonglong2 hv = *(const ulonglong2*)(hr + k);
                a0 = fma2(w0[6+k], hv.x, a0); a0 = fma2(w0[6+k+1], hv.y, a0);
                a1 = fma2(w1[6+k], hv.x, a1); a1 = fma2(w1[6+k+1], hv.y, a1);
            }
            gA[j] = hadd2(a0);
            gB[j] = hadd2(a1);
        }

        // ---- exchange + epilogue, pairs p=0 (batches j 0/2) and p=1 (j 1/3) ----
        #pragma unroll
        for (int p = 0; p < 2; p++) {
            // static-index selects (gh is uniform per thread)
            float sendA = gh ? gA[p]     : gA[2 + p];   // my row0 gate for partner's batch
            float sendB = gh ? gB[p]     : gB[2 + p];
            float ownA  = gh ? gA[2 + p] : gA[p];       // my row0 gate for my batch
            float ownB  = gh ? gB[2 + p] : gB[p];
            float recvA = __shfl_xor_sync(0xffffffffu, sendA, 1);
            float recvB = __shfl_xor_sync(0xffffffffu, sendB, 1);
            // gh0: own=(i,g), recv=(f,o); gh1: own=(f,o), recv=(i,g)
            float gi = gh ? recvA : ownA;
            float gg = gh ? recvB : ownB;
            float gf = gh ? ownA  : recvA;
            float go = gh ? ownB  : recvB;
            float c  = p ? c1 : c0;
            c = sigA(gf) * c + sigA(gi) * tanhA(gg);
            if (p) c1 = c; else c0 = c;
            float h = sigA(go) * tanhA(c);
            hbuf[nxt][(q4 + 2 * gh + p) * LSTM_H + u] = h;
        }
        group_bar(barid);
    }

    // ---- output Linear (final h in hbuf[0]; group-local, last bar covers) ----
    {
        const int bl = ltid / 10, k = ltid - (ltid / 10) * 10;  // 16 x 10 = 160
        const int b  = gid * 16 + bl;
        float sum = b_out[k];
        #pragma unroll
        for (int j = 0; j < LSTM_H; j++)
            sum = fmaf(hbuf[0][b * LSTM_H + j], w_out[k * LSTM_H + j], sum);
        out[(long)(b0 + b) * 10 + k] = sum;
    }
}

extern "C" void kernel_launch(void* const* d_in, const int* in_sizes, int n_in,
                              void* d_out, int out_size)
{
    const float* x     = (const float*)d_in[0];
    const float* w_ih  = (const float*)d_in[1];
    const float* w_hh  = (const float*)d_in[2];
    const float* b_ih  = (const float*)d_in[3];
    const float* b_hh  = (const float*)d_in[4];
    const float* w_out = (const float*)d_in[5];
    const float* b_out = (const float*)d_in[6];
    float* out = (float*)d_out;

    lstm_kernel<<<GRID, THREADS>>>(x, w_ih, w_hh, b_ih, b_hh, w_out, b_out, out);
}